// round 16
// baseline (speedup 1.0000x reference)
#include <cuda_runtime.h>
#include <cuda_fp16.h>
#include <cstdint>
#include <cstddef>

// Problem dims (fixed by the dataset)
#define MDIM 8192
#define KDIM 4096
#define NDIM 11008

// GEMM tiling: 128x128 CTA tile, 2 CTAs/SM, 4 warps (2x2), warp 64x64
#define BM 128
#define BN 128
#define BK 64
#define KTILES (KDIM / BK)            // 64
#define STAGES 3
#define A_STAGE_BYTES (BM * BK * 2)   // 16384
#define B_STAGE_BYTES (BN * BK * 2)   // 16384
#define STAGE_BYTES (A_STAGE_BYTES + B_STAGE_BYTES)  // 32768
#define SMEM_DYN (STAGES * STAGE_BYTES)              // 98304 per CTA

// Scratch: converted fp16 operands. Static device globals (no cudaMalloc).
__device__ __align__(1024) __half g_A[(size_t)MDIM * KDIM]; // quantized acts (exact ints)
__device__ __align__(1024) __half g_B[(size_t)NDIM * KDIM]; // weights (exact ints)

// SW128 swizzle for 128-byte rows
#define SWZ(o) ((o) ^ (((o) >> 3) & 0x70))

__device__ __forceinline__ uint32_t smem_u32(const void* p) {
    return (uint32_t)__cvta_generic_to_shared(p);
}
__device__ __forceinline__ void cp16(uint32_t dst, const void* src) {
    asm volatile("cp.async.cg.shared.global [%0], [%1], 16;" :: "r"(dst), "l"(src));
}
__device__ __forceinline__ void ldsm4(uint32_t* r, uint32_t addr) {
    asm volatile("ldmatrix.sync.aligned.m8n8.x4.shared.b16 {%0,%1,%2,%3}, [%4];"
                 : "=r"(r[0]), "=r"(r[1]), "=r"(r[2]), "=r"(r[3]) : "r"(addr));
}
__device__ __forceinline__ void mma16816(float* c, const uint32_t* a, const uint32_t* b) {
    asm volatile(
        "mma.sync.aligned.m16n8k16.row.col.f32.f16.f16.f32 "
        "{%0,%1,%2,%3}, {%4,%5,%6,%7}, {%8,%9}, {%0,%1,%2,%3};"
        : "+f"(c[0]), "+f"(c[1]), "+f"(c[2]), "+f"(c[3])
        : "r"(a[0]), "r"(a[1]), "r"(a[2]), "r"(a[3]), "r"(b[0]), "r"(b[1]));
}
__device__ __forceinline__ void stcs2(float* p, float xv, float yv) {
    asm volatile("st.global.cs.v2.f32 [%0], {%1, %2};" :: "l"(p), "f"(xv), "f"(yv) : "memory");
}

// ---------------------------------------------------------------------------
// Merged conversion pre-pass, MLP=4 per thread (latency-bound -> batch loads).
// MLP=8 regressed 50% via DVFS clock drag (R13) — MLP=4 is the knee.
// Block geometry: 256 threads x 4 vec4s = 1024 vec4s per block.
//   N4X = 8388608  = 8192 blocks exactly   (x -> g_A)
//   N4W = 11272192 = 11008 blocks exactly  (w -> g_B)
// No boundary predicates; loads/stores interleaved by 256 for coalescing.
// ---------------------------------------------------------------------------
#define XBLK 8192
#define WBLK 11008

__global__ void __launch_bounds__(256) k_convert(const float4* __restrict__ x,
                                                 const int4* __restrict__ w) {
    const int tid = threadIdx.x;
    const int bid = blockIdx.x;
    if (bid < XBLK) {
        const float4* src = x + (size_t)bid * 1024 + tid;
        float4 v[4];
#pragma unroll
        for (int j = 0; j < 4; j++) v[j] = __ldcs(src + j * 256);   // MLP=4
        uint2* dst = (uint2*)g_A + (size_t)bid * 1024 + tid;
#pragma unroll
        for (int j = 0; j < 4; j++) {
            float a = fminf(fmaxf(rintf(__fdiv_rn(v[j].x, 0.02f)), -32768.f), 32767.f);
            float b = fminf(fmaxf(rintf(__fdiv_rn(v[j].y, 0.02f)), -32768.f), 32767.f);
            float c = fminf(fmaxf(rintf(__fdiv_rn(v[j].z, 0.02f)), -32768.f), 32767.f);
            float d = fminf(fmaxf(rintf(__fdiv_rn(v[j].w, 0.02f)), -32768.f), 32767.f);
            __half2 h0 = __floats2half2_rn(a, b);
            __half2 h1 = __floats2half2_rn(c, d);
            uint2 o;
            o.x = *(uint32_t*)&h0;
            o.y = *(uint32_t*)&h1;
            dst[j * 256] = o;
        }
    } else {
        const int4* src = w + (size_t)(bid - XBLK) * 1024 + tid;
        int4 v[4];
#pragma unroll
        for (int j = 0; j < 4; j++) v[j] = __ldcs(src + j * 256);   // MLP=4
        uint2* dst = (uint2*)g_B + (size_t)(bid - XBLK) * 1024 + tid;
#pragma unroll
        for (int j = 0; j < 4; j++) {
            __half2 h0 = __halves2half2(__int2half_rn(v[j].x), __int2half_rn(v[j].y));
            __half2 h1 = __halves2half2(__int2half_rn(v[j].z), __int2half_rn(v[j].w));
            uint2 o;
            o.x = *(uint32_t*)&h0;
            o.y = *(uint32_t*)&h1;
            dst[j * 256] = o;
        }
    }
}

// ---------------------------------------------------------------------------
// GEMM: 128x128 CTA tile, mma.sync m16n8k16 (HMMA), 3-stage cp.async pipeline,
// 2 CTAs/SM, operand double-buffering, pipeline turn hoisted into the ks=3
// slot. One tile per CTA — the mainloop MUST stay the sole top-level body of
// the kernel (persistence variants R10/R11 degrade ptxas codegen by >10%).
// BYTE-FROZEN R9/R12 winner. At ~98% of the mma.sync issue floor.
// ---------------------------------------------------------------------------

__device__ __forceinline__ void load_stage(uint32_t sb, int s, int kt,
                                           int tileM, int tileN, int tid) {
    uint32_t stA = sb + (uint32_t)s * STAGE_BYTES;
    uint32_t stB = stA + A_STAGE_BYTES;
    const char* gA = (const char*)g_A + ((size_t)tileM * BM * KDIM + (size_t)kt * BK) * 2;
    const char* gB = (const char*)g_B + ((size_t)tileN * BN * KDIM + (size_t)kt * BK) * 2;
#pragma unroll
    for (int i = 0; i < (A_STAGE_BYTES / 16 / 128); i++) { // 8
        int c = tid + i * 128;
        int row = c >> 3;
        int col = (c & 7) << 4;
        cp16(stA + SWZ(row * 128 + col), gA + (size_t)row * (KDIM * 2) + col);
    }
#pragma unroll
    for (int i = 0; i < (B_STAGE_BYTES / 16 / 128); i++) { // 8
        int c = tid + i * 128;
        int row = c >> 3;
        int col = (c & 7) << 4;
        cp16(stB + SWZ(row * 128 + col), gB + (size_t)row * (KDIM * 2) + col);
    }
    asm volatile("cp.async.commit_group;" ::: "memory");
}

__global__ void __launch_bounds__(128, 2)
gemm_hmma(float* __restrict__ out,
          const float* __restrict__ scale,
          const float* __restrict__ bias) {
    extern __shared__ char dsmem[];
    __shared__ float s_sc[BN];
    __shared__ float s_bi[BN];

    const int tid = threadIdx.x;
    const int tileM = blockIdx.x;  // 0..63 (fastest -> wave shares tileN band)
    const int tileN = blockIdx.y;  // 0..85

    const uint32_t sb = smem_u32(dsmem);

    const int wid = tid >> 5;
    const int lane = tid & 31;
    const int wm = wid & 1;        // 0..1  M
    const int wn = wid >> 1;       // 0..1  N
    const int grp = lane >> 3;
    const int r = lane & 7;
    const uint32_t xorv = (uint32_t)(r * 16);

    const int a_moff = (grp & 1) * 8;
    const int a_kb = (grp >> 1) * 16;
    const int b_noff = (grp >> 1) * 8;
    const int b_kb = (grp & 1) * 16;

    // Dequant coefficients for this N band -> shared (overlapped with prologue).
    {
        int n = tileN * BN + tid;
        s_sc[tid] = 0.02f * __ldg(scale + n);
        s_bi[tid] = __ldg(bias + n);
    }

    uint32_t aRowTerm[4], bRowTerm[4];
#pragma unroll
    for (int mt = 0; mt < 4; mt++)
        aRowTerm[mt] = (uint32_t)((wm * 64 + mt * 16 + a_moff + r) * 128);
#pragma unroll
    for (int nt2 = 0; nt2 < 4; nt2++)
        bRowTerm[nt2] = (uint32_t)(A_STAGE_BYTES + (wn * 64 + nt2 * 16 + b_noff + r) * 128);

    float acc[4][8][4];
#pragma unroll
    for (int mt = 0; mt < 4; mt++)
#pragma unroll
        for (int nt = 0; nt < 8; nt++)
#pragma unroll
            for (int j = 0; j < 4; j++) acc[mt][nt][j] = 0.f;

    // Prologue: fill all 3 stages, then arm the ks=0 operands of kt=0.
    load_stage(sb, 0, 0, tileM, tileN, tid);
    load_stage(sb, 1, 1, tileM, tileN, tid);
    load_stage(sb, 2, 2, tileM, tileN, tid);

    uint32_t abuf[2][4][4], bbuf[2][4][4];

    asm volatile("cp.async.wait_group 2;" ::: "memory");  // g0 complete
    __syncthreads();
    {
        const uint32_t stg0 = sb;
        const uint32_t akcol = (uint32_t)a_kb ^ xorv;
        const uint32_t bkcol = (uint32_t)b_kb ^ xorv;
#pragma unroll
        for (int mt = 0; mt < 4; mt++) ldsm4(abuf[0][mt], stg0 + aRowTerm[mt] + akcol);
#pragma unroll
        for (int nt2 = 0; nt2 < 4; nt2++) ldsm4(bbuf[0][nt2], stg0 + bRowTerm[nt2] + bkcol);
    }

    for (int kt = 0; kt < KTILES; kt++) {
        const uint32_t stg = sb + (uint32_t)(kt % STAGES) * STAGE_BYTES;
#pragma unroll
        for (int ks = 0; ks < BK / 16; ks++) {
            const int cur = ks & 1;
            if (ks < BK / 16 - 1) {
                // Prefetch ks+1 operands of the current stage.
                const int nxt = cur ^ 1;
                const uint32_t akcol = (uint32_t)((ks + 1) * 32 + a_kb) ^ xorv;
                const uint32_t bkcol = (uint32_t)((ks + 1) * 32 + b_kb) ^ xorv;
#pragma unroll
                for (int mt = 0; mt < 4; mt++)
                    ldsm4(abuf[nxt][mt], stg + aRowTerm[mt] + akcol);
#pragma unroll
                for (int nt2 = 0; nt2 < 4; nt2++)
                    ldsm4(bbuf[nxt][nt2], stg + bRowTerm[nt2] + bkcol);
            } else if (kt < KTILES - 1) {
                // Pipeline turn: ensure stage kt+1 is loaded, recycle stage kt,
                // and arm the next kt's ks=0 operands BEFORE the ks=3 MMA block
                // so their LDS latency drains behind it.
                if (kt < KTILES - 2) {
                    asm volatile("cp.async.wait_group 1;" ::: "memory");
                } else {
                    asm volatile("cp.async.wait_group 0;" ::: "memory");
                }
                __syncthreads();
                if (kt + 3 < KTILES)
                    load_stage(sb, (kt + 3) % STAGES, kt + 3, tileM, tileN, tid);
                const uint32_t nstg = sb + (uint32_t)((kt + 1) % STAGES) * STAGE_BYTES;
                const uint32_t akcol = (uint32_t)a_kb ^ xorv;
                const uint32_t bkcol = (uint32_t)b_kb ^ xorv;
#pragma unroll
                for (int mt = 0; mt < 4; mt++)
                    ldsm4(abuf[0][mt], nstg + aRowTerm[mt] + akcol);
#pragma unroll
                for (int nt2 = 0; nt2 < 4; nt2++)
                    ldsm4(bbuf[0][nt2], nstg + bRowTerm[nt2] + bkcol);
            }
#pragma unroll
            for (int mt = 0; mt < 4; mt++)
#pragma unroll
                for (int nt = 0; nt < 8; nt++)
                    mma16816(acc[mt][nt], abuf[cur][mt], &bbuf[cur][nt >> 1][(nt & 1) * 2]);
        }
    }

    // Epilogue: fused per-channel dequant + bias; streaming stores (output is
    // never re-read — keep it from write-allocating over A/B in L2).
    {
        const int cloc = wn * 64 + (lane & 3) * 2;
        const int rbase = tileM * BM + wm * 64 + (lane >> 2);
        const int cg = tileN * BN;
#pragma unroll
        for (int mt = 0; mt < 4; mt++) {
            float* op0 = out + (size_t)(rbase + mt * 16) * NDIM + cg;
            float* op1 = op0 + (size_t)8 * NDIM;
#pragma unroll
            for (int nt = 0; nt < 8; nt++) {
                int c = cloc + nt * 8;
                float sc0 = s_sc[c], sc1 = s_sc[c + 1];
                float bi0 = s_bi[c], bi1 = s_bi[c + 1];
                stcs2(op0 + c, acc[mt][nt][0] * sc0 + bi0, acc[mt][nt][1] * sc1 + bi1);
                stcs2(op1 + c, acc[mt][nt][2] * sc0 + bi0, acc[mt][nt][3] * sc1 + bi1);
            }
        }
    }
}

// ---------------------------------------------------------------------------
// Launch
// ---------------------------------------------------------------------------

extern "C" void kernel_launch(void* const* d_in, const int* in_sizes, int n_in,
                              void* d_out, int out_size) {
    const float* x     = (const float*)d_in[0];
    const int*   w     = (const int*)d_in[1];
    const float* scale = (const float*)d_in[2];
    const float* bias  = (const float*)d_in[3];
    float* out = (float*)d_out;

    cudaFuncSetAttribute(gemm_hmma, cudaFuncAttributeMaxDynamicSharedMemorySize, SMEM_DYN);

    {
        k_convert<<<XBLK + WBLK, 256>>>((const float4*)x, (const int4*)w);
    }
    {
        dim3 grid(MDIM / BM, NDIM / BN);      // 64 x 86
        gemm_hmma<<<grid, 128, SMEM_DYN>>>(out, scale, bias);
    }
}

// round 17
// speedup vs baseline: 1.5281x; 1.5281x over previous
#include <cuda_runtime.h>
#include <cuda_fp16.h>
#include <cstdint>
#include <cstddef>

// Problem dims (fixed by the dataset)
#define MDIM 8192
#define KDIM 4096
#define NDIM 11008

// GEMM tiling: 128x128 CTA tile, 2 CTAs/SM, 4 warps (2x2), warp 64x64
#define BM 128
#define BN 128
#define BK 64
#define KTILES (KDIM / BK)            // 64
#define STAGES 3
#define A_STAGE_BYTES (BM * BK * 2)   // 16384
#define B_STAGE_BYTES (BN * BK * 2)   // 16384
#define STAGE_BYTES (A_STAGE_BYTES + B_STAGE_BYTES)  // 32768
#define SMEM_DYN (STAGES * STAGE_BYTES)              // 98304 per CTA

// Scratch: converted fp16 operands. Static device globals (no cudaMalloc).
__device__ __align__(1024) __half g_A[(size_t)MDIM * KDIM]; // quantized acts (exact ints)
__device__ __align__(1024) __half g_B[(size_t)NDIM * KDIM]; // weights (exact ints)

// SW128 swizzle for 128-byte rows
#define SWZ(o) ((o) ^ (((o) >> 3) & 0x70))

__device__ __forceinline__ uint32_t smem_u32(const void* p) {
    return (uint32_t)__cvta_generic_to_shared(p);
}
__device__ __forceinline__ void cp16(uint32_t dst, const void* src) {
    asm volatile("cp.async.cg.shared.global [%0], [%1], 16;" :: "r"(dst), "l"(src));
}
__device__ __forceinline__ void ldsm4(uint32_t* r, uint32_t addr) {
    asm volatile("ldmatrix.sync.aligned.m8n8.x4.shared.b16 {%0,%1,%2,%3}, [%4];"
                 : "=r"(r[0]), "=r"(r[1]), "=r"(r[2]), "=r"(r[3]) : "r"(addr));
}
__device__ __forceinline__ void mma16816(float* c, const uint32_t* a, const uint32_t* b) {
    asm volatile(
        "mma.sync.aligned.m16n8k16.row.col.f32.f16.f16.f32 "
        "{%0,%1,%2,%3}, {%4,%5,%6,%7}, {%8,%9}, {%0,%1,%2,%3};"
        : "+f"(c[0]), "+f"(c[1]), "+f"(c[2]), "+f"(c[3])
        : "r"(a[0]), "r"(a[1]), "r"(a[2]), "r"(a[3]), "r"(b[0]), "r"(b[1]));
}
__device__ __forceinline__ void stcs2(float* p, float xv, float yv) {
    asm volatile("st.global.cs.v2.f32 [%0], {%1, %2};" :: "l"(p), "f"(xv), "f"(yv) : "memory");
}

// ---------------------------------------------------------------------------
// Merged conversion pre-pass, MLP=4 per thread (latency-bound -> batch loads).
// Block geometry: 256 threads x 4 vec4s = 1024 vec4s per block.
//   N4X = 8388608  = 8192 blocks exactly   (x -> g_A)
//   N4W = 11272192 = 11008 blocks exactly  (w -> g_B)
// No boundary predicates; loads/stores interleaved by 256 for coalescing.
// ---------------------------------------------------------------------------
#define XBLK 8192
#define WBLK 11008

__global__ void __launch_bounds__(256) k_convert(const float4* __restrict__ x,
                                                 const int4* __restrict__ w) {
    const int tid = threadIdx.x;
    const int bid = blockIdx.x;
    if (bid < XBLK) {
        const float4* src = x + (size_t)bid * 1024 + tid;
        float4 v[4];
#pragma unroll
        for (int j = 0; j < 4; j++) v[j] = __ldcs(src + j * 256);   // MLP=4
        uint2* dst = (uint2*)g_A + (size_t)bid * 1024 + tid;
#pragma unroll
        for (int j = 0; j < 4; j++) {
            float a = fminf(fmaxf(rintf(__fdiv_rn(v[j].x, 0.02f)), -32768.f), 32767.f);
            float b = fminf(fmaxf(rintf(__fdiv_rn(v[j].y, 0.02f)), -32768.f), 32767.f);
            float c = fminf(fmaxf(rintf(__fdiv_rn(v[j].z, 0.02f)), -32768.f), 32767.f);
            float d = fminf(fmaxf(rintf(__fdiv_rn(v[j].w, 0.02f)), -32768.f), 32767.f);
            __half2 h0 = __floats2half2_rn(a, b);
            __half2 h1 = __floats2half2_rn(c, d);
            uint2 o;
            o.x = *(uint32_t*)&h0;
            o.y = *(uint32_t*)&h1;
            dst[j * 256] = o;
        }
    } else {
        const int4* src = w + (size_t)(bid - XBLK) * 1024 + tid;
        int4 v[4];
#pragma unroll
        for (int j = 0; j < 4; j++) v[j] = __ldcs(src + j * 256);   // MLP=4
        uint2* dst = (uint2*)g_B + (size_t)(bid - XBLK) * 1024 + tid;
#pragma unroll
        for (int j = 0; j < 4; j++) {
            __half2 h0 = __halves2half2(__int2half_rn(v[j].x), __int2half_rn(v[j].y));
            __half2 h1 = __halves2half2(__int2half_rn(v[j].z), __int2half_rn(v[j].w));
            uint2 o;
            o.x = *(uint32_t*)&h0;
            o.y = *(uint32_t*)&h1;
            dst[j * 256] = o;
        }
    }
}

// ---------------------------------------------------------------------------
// GEMM: 128x128 CTA tile, mma.sync m16n8k16 (HMMA), 3-stage cp.async pipeline,
// 2 CTAs/SM, operand double-buffering, pipeline turn hoisted into the ks=3
// slot. One tile per CTA — the mainloop MUST stay the sole top-level body of
// the kernel (persistence variants R10/R11 degrade ptxas codegen by >10%).
// BYTE-FROZEN R9/R12/R15 winner. At ~98% of the mma.sync issue floor.
// Wall-time is session-clock bimodal (~1453us fast / ~2220us slow) with
// IDENTICAL cycle metrics — environment, not kernel (R13 vs R15 vs R16).
// ---------------------------------------------------------------------------

__device__ __forceinline__ void load_stage(uint32_t sb, int s, int kt,
                                           int tileM, int tileN, int tid) {
    uint32_t stA = sb + (uint32_t)s * STAGE_BYTES;
    uint32_t stB = stA + A_STAGE_BYTES;
    const char* gA = (const char*)g_A + ((size_t)tileM * BM * KDIM + (size_t)kt * BK) * 2;
    const char* gB = (const char*)g_B + ((size_t)tileN * BN * KDIM + (size_t)kt * BK) * 2;
#pragma unroll
    for (int i = 0; i < (A_STAGE_BYTES / 16 / 128); i++) { // 8
        int c = tid + i * 128;
        int row = c >> 3;
        int col = (c & 7) << 4;
        cp16(stA + SWZ(row * 128 + col), gA + (size_t)row * (KDIM * 2) + col);
    }
#pragma unroll
    for (int i = 0; i < (B_STAGE_BYTES / 16 / 128); i++) { // 8
        int c = tid + i * 128;
        int row = c >> 3;
        int col = (c & 7) << 4;
        cp16(stB + SWZ(row * 128 + col), gB + (size_t)row * (KDIM * 2) + col);
    }
    asm volatile("cp.async.commit_group;" ::: "memory");
}

__global__ void __launch_bounds__(128, 2)
gemm_hmma(float* __restrict__ out,
          const float* __restrict__ scale,
          const float* __restrict__ bias) {
    extern __shared__ char dsmem[];
    __shared__ float s_sc[BN];
    __shared__ float s_bi[BN];

    const int tid = threadIdx.x;
    const int tileM = blockIdx.x;  // 0..63 (fastest -> wave shares tileN band)
    const int tileN = blockIdx.y;  // 0..85

    const uint32_t sb = smem_u32(dsmem);

    const int wid = tid >> 5;
    const int lane = tid & 31;
    const int wm = wid & 1;        // 0..1  M
    const int wn = wid >> 1;       // 0..1  N
    const int grp = lane >> 3;
    const int r = lane & 7;
    const uint32_t xorv = (uint32_t)(r * 16);

    const int a_moff = (grp & 1) * 8;
    const int a_kb = (grp >> 1) * 16;
    const int b_noff = (grp >> 1) * 8;
    const int b_kb = (grp & 1) * 16;

    // Dequant coefficients for this N band -> shared (overlapped with prologue).
    {
        int n = tileN * BN + tid;
        s_sc[tid] = 0.02f * __ldg(scale + n);
        s_bi[tid] = __ldg(bias + n);
    }

    uint32_t aRowTerm[4], bRowTerm[4];
#pragma unroll
    for (int mt = 0; mt < 4; mt++)
        aRowTerm[mt] = (uint32_t)((wm * 64 + mt * 16 + a_moff + r) * 128);
#pragma unroll
    for (int nt2 = 0; nt2 < 4; nt2++)
        bRowTerm[nt2] = (uint32_t)(A_STAGE_BYTES + (wn * 64 + nt2 * 16 + b_noff + r) * 128);

    float acc[4][8][4];
#pragma unroll
    for (int mt = 0; mt < 4; mt++)
#pragma unroll
        for (int nt = 0; nt < 8; nt++)
#pragma unroll
            for (int j = 0; j < 4; j++) acc[mt][nt][j] = 0.f;

    // Prologue: fill all 3 stages, then arm the ks=0 operands of kt=0.
    load_stage(sb, 0, 0, tileM, tileN, tid);
    load_stage(sb, 1, 1, tileM, tileN, tid);
    load_stage(sb, 2, 2, tileM, tileN, tid);

    uint32_t abuf[2][4][4], bbuf[2][4][4];

    asm volatile("cp.async.wait_group 2;" ::: "memory");  // g0 complete
    __syncthreads();
    {
        const uint32_t stg0 = sb;
        const uint32_t akcol = (uint32_t)a_kb ^ xorv;
        const uint32_t bkcol = (uint32_t)b_kb ^ xorv;
#pragma unroll
        for (int mt = 0; mt < 4; mt++) ldsm4(abuf[0][mt], stg0 + aRowTerm[mt] + akcol);
#pragma unroll
        for (int nt2 = 0; nt2 < 4; nt2++) ldsm4(bbuf[0][nt2], stg0 + bRowTerm[nt2] + bkcol);
    }

    for (int kt = 0; kt < KTILES; kt++) {
        const uint32_t stg = sb + (uint32_t)(kt % STAGES) * STAGE_BYTES;
#pragma unroll
        for (int ks = 0; ks < BK / 16; ks++) {
            const int cur = ks & 1;
            if (ks < BK / 16 - 1) {
                // Prefetch ks+1 operands of the current stage.
                const int nxt = cur ^ 1;
                const uint32_t akcol = (uint32_t)((ks + 1) * 32 + a_kb) ^ xorv;
                const uint32_t bkcol = (uint32_t)((ks + 1) * 32 + b_kb) ^ xorv;
#pragma unroll
                for (int mt = 0; mt < 4; mt++)
                    ldsm4(abuf[nxt][mt], stg + aRowTerm[mt] + akcol);
#pragma unroll
                for (int nt2 = 0; nt2 < 4; nt2++)
                    ldsm4(bbuf[nxt][nt2], stg + bRowTerm[nt2] + bkcol);
            } else if (kt < KTILES - 1) {
                // Pipeline turn: ensure stage kt+1 is loaded, recycle stage kt,
                // and arm the next kt's ks=0 operands BEFORE the ks=3 MMA block
                // so their LDS latency drains behind it.
                if (kt < KTILES - 2) {
                    asm volatile("cp.async.wait_group 1;" ::: "memory");
                } else {
                    asm volatile("cp.async.wait_group 0;" ::: "memory");
                }
                __syncthreads();
                if (kt + 3 < KTILES)
                    load_stage(sb, (kt + 3) % STAGES, kt + 3, tileM, tileN, tid);
                const uint32_t nstg = sb + (uint32_t)((kt + 1) % STAGES) * STAGE_BYTES;
                const uint32_t akcol = (uint32_t)a_kb ^ xorv;
                const uint32_t bkcol = (uint32_t)b_kb ^ xorv;
#pragma unroll
                for (int mt = 0; mt < 4; mt++)
                    ldsm4(abuf[0][mt], nstg + aRowTerm[mt] + akcol);
#pragma unroll
                for (int nt2 = 0; nt2 < 4; nt2++)
                    ldsm4(bbuf[0][nt2], nstg + bRowTerm[nt2] + bkcol);
            }
#pragma unroll
            for (int mt = 0; mt < 4; mt++)
#pragma unroll
                for (int nt = 0; nt < 8; nt++)
                    mma16816(acc[mt][nt], abuf[cur][mt], &bbuf[cur][nt >> 1][(nt & 1) * 2]);
        }
    }

    // Epilogue: fused per-channel dequant + bias; streaming stores (output is
    // never re-read — keep it from write-allocating over A/B in L2).
    {
        const int cloc = wn * 64 + (lane & 3) * 2;
        const int rbase = tileM * BM + wm * 64 + (lane >> 2);
        const int cg = tileN * BN;
#pragma unroll
        for (int mt = 0; mt < 4; mt++) {
            float* op0 = out + (size_t)(rbase + mt * 16) * NDIM + cg;
            float* op1 = op0 + (size_t)8 * NDIM;
#pragma unroll
            for (int nt = 0; nt < 8; nt++) {
                int c = cloc + nt * 8;
                float sc0 = s_sc[c], sc1 = s_sc[c + 1];
                float bi0 = s_bi[c], bi1 = s_bi[c + 1];
                stcs2(op0 + c, acc[mt][nt][0] * sc0 + bi0, acc[mt][nt][1] * sc1 + bi1);
                stcs2(op1 + c, acc[mt][nt][2] * sc0 + bi0, acc[mt][nt][3] * sc1 + bi1);
            }
        }
    }
}

// ---------------------------------------------------------------------------
// Launch
// ---------------------------------------------------------------------------

extern "C" void kernel_launch(void* const* d_in, const int* in_sizes, int n_in,
                              void* d_out, int out_size) {
    const float* x     = (const float*)d_in[0];
    const int*   w     = (const int*)d_in[1];
    const float* scale = (const float*)d_in[2];
    const float* bias  = (const float*)d_in[3];
    float* out = (float*)d_out;

    cudaFuncSetAttribute(gemm_hmma, cudaFuncAttributeMaxDynamicSharedMemorySize, SMEM_DYN);

    {
        k_convert<<<XBLK + WBLK, 256>>>((const float4*)x, (const int4*)w);
    }
    {
        dim3 grid(MDIM / BM, NDIM / BN);      // 64 x 86
        gemm_hmma<<<grid, 128, SMEM_DYN>>>(out, scale, bias);
    }
}